// round 15
// baseline (speedup 1.0000x reference)
#include <cuda_runtime.h>

// Problem constants
#define CTC_B 256
#define CTC_T 256
#define CTC_C 512
#define CTC_L 64
#define ROWE  66            // g_emit floats per row: 64 label probs + blank + pad
#define LOG2E 1.4426950408889634f
#define LN2   0.6931471805599453f
#define DPCH  8             // rows per chunk
#define NCHNK (CTC_T / DPCH)          // 32 chunks per batch
#define ESENT (-(1 << 28))  // exponent sentinel for massless lanes

__device__ float g_emit[(size_t)CTC_B * CTC_T * ROWE];   // softmax PROBS (~17 MB)
__device__ float g_nll[CTC_B];
__device__ unsigned int g_count = 0;
__device__ int g_flag[CTC_B * NCHNK];    // chunk-ready flags (zero-init; re-zeroed)

__device__ __forceinline__ float warpsum(float v) {
#pragma unroll
    for (int o = 16; o; o >>= 1) v += __shfl_xor_sync(0xffffffffu, v, o);
    return v;
}
__device__ __forceinline__ float warpmaxf(float v) {
#pragma unroll
    for (int o = 16; o; o >>= 1) v = fmaxf(v, __shfl_xor_sync(0xffffffffu, v, o));
    return v;
}
__device__ __forceinline__ void barsync(int id, int cnt) {
    asm volatile("bar.sync %0, %1;" :: "r"(id), "r"(cnt) : "memory");
}

// ONE kernel, heterogeneous grid:
//   blocks [0, CTC_B)        : DP blocks (warps 0/1 = fwd/bwd, rest exit)
//   blocks [CTC_B, CTC_B+8192): emit blocks (8 warps, 8 rows each)
// Emit block e: batch = e & 255, schedule slot cc = e >> 8, chunk
// tc = front/back interleave of cc so fwd and bwd frontiers advance together.
__global__ void __launch_bounds__(256) ctc_fused_kernel(
    const float* __restrict__ logits,
    const int* __restrict__ labels,
    const int* __restrict__ label_length,
    const int* __restrict__ logit_length,
    float* __restrict__ out)
{
    __shared__ float srow[8][CTC_C];
    __shared__ int   slab[CTC_L];
    __shared__ float sv[2][5][32];
    __shared__ int   sEx[2][32];

    const int tid  = threadIdx.x;
    const int w    = tid >> 5;
    const int lane = tid & 31;

    if (blockIdx.x >= CTC_B) {
        // ===================== EMIT ROLE (validated R8-R14 math) =====================
        const int e  = blockIdx.x - CTC_B;
        const int b  = e & (CTC_B - 1);
        const int cc = e >> 8;                                   // 0..31
        const int tc = (cc & 1) ? (NCHNK - 1 - (cc >> 1)) : (cc >> 1);

        if (tid < CTC_L) slab[tid] = labels[b * CTC_L + tid];

        const int row_id = b * CTC_T + tc * DPCH + w;            // 8 rows per block
        const float4* row4 = (const float4*)(logits + (size_t)row_id * CTC_C);
        float4 v[4];
#pragma unroll
        for (int k = 0; k < 4; k++) v[k] = row4[k * 32 + lane];

        float s = 0.f;
#pragma unroll
        for (int k = 0; k < 4; k++) {
            const float e0 = exp2f(v[k].x * LOG2E);
            const float e1 = exp2f(v[k].y * LOG2E);
            const float e2 = exp2f(v[k].z * LOG2E);
            const float e3 = exp2f(v[k].w * LOG2E);
            const int i4 = (k * 32 + lane) * 4;
            srow[w][i4 + 0] = e0; srow[w][i4 + 1] = e1;
            srow[w][i4 + 2] = e2; srow[w][i4 + 3] = e3;
            s += e0 + e1 + e2 + e3;
        }
        s = warpsum(s);
        const float rcp = __frcp_rn(s);
        __syncthreads();                        // slab + srow visibility

        float* eout = g_emit + (size_t)row_id * ROWE;
        eout[lane]      = srow[w][slab[lane]]      * rcp;
        eout[32 + lane] = srow[w][slab[32 + lane]] * rcp;
        if (lane == 0)
            eout[CTC_L] = srow[w][CTC_C - 1] * rcp;              // blank

        // release: every thread fences its own writes, then one flag store
        __threadfence();
        __syncthreads();
        if (tid == 0)
            *(volatile int*)&g_flag[b * NCHNK + tc] = 1;
        return;
    }

    // ===================== DP ROLE (validated R13 math + flag waits) ==============
    if (w >= 2) return;                          // only warps 0 (fwd) and 1 (bwd)
    const int b = blockIdx.x;

    if (tid < CTC_L) slab[tid] = labels[b * CTC_L + tid];
    barsync(1, 64);

    const int tl = logit_length[b];              // == 256 here
    const int ll = label_length[b];
    const int tm = tl >> 1;
    const int NIT = tm / DPCH;                   // 16 chunks per direction

    const float sk1 = ((4 * lane + 1) >= 3 && slab[2 * lane] != slab[2 * lane - 1]) ? 1.f : 0.f;
    const float sk3 = (slab[2 * lane + 1] != slab[2 * lane]) ? 1.f : 0.f;

    const float* ebase = g_emit + (size_t)b * CTC_T * ROWE;
    const volatile int* flags = (const volatile int*)(g_flag + b * NCHNK);

    auto waitflag = [&](int tc) {
        while (flags[tc] == 0) __nanosleep(64);
        __threadfence();                         // acquire
    };

    float2 e2A[DPCH], e2B[DPCH];
    float  ebA[DPCH], ebB[DPCH];

    float a0, a1, a2, a3, a4;
    int E;

    // branchless per-lane renorm (m==0 -> ex=-127, sentinel drifts lower)
    auto renorm = [&]() {
        const float m = fmaxf(fmaxf(fmaxf(a0, a1), fmaxf(a2, a3)), a4);
        const int ex = (__float_as_int(m) >> 23) - 127;
        const float r = __int_as_float((127 - ex) << 23);
        a0 *= r; a1 *= r; a2 *= r; a3 *= r; a4 *= r;
        E += ex;
    };

    if (w == 0) {
        // ---------------- FORWARD WARP ----------------
        auto load_f = [&](int k, float2 (&e2)[DPCH], float (&eb)[DPCH]) {
#pragma unroll
            for (int j = 0; j < DPCH; j++) {
                const float* r = ebase + (size_t)(k * DPCH + j) * ROWE;
                e2[j] = __ldg((const float2*)r + lane);
                eb[j] = __ldg(r + CTC_L);
            }
        };
        auto fwd_step = [&](const float2 e2, const float eb) {
            float am1 = __shfl_up_sync(0xffffffffu, a3, 1);
            int   Ep  = __shfl_up_sync(0xffffffffu, E,  1);
            am1 = (lane == 0) ? 0.f : am1;
            Ep  = (lane == 0) ? E   : Ep;
            const int   En = max(E, Ep);
            const float f1 = __int_as_float(max(127 + (E  - En), 0) << 23);
            const float f2 = __int_as_float(max(127 + (Ep - En), 0) << 23);
            am1 *= f2;
            a0 *= f1; a1 *= f1; a2 *= f1; a3 *= f1; a4 *= f1;
            E = En;
            const float na0 = (a0 + am1)              * eb;
            const float na1 = fmaf(sk1, am1, a1 + a0) * e2.x;
            const float na2 = (a2 + a1)               * eb;
            const float na3 = fmaf(sk3, a1, a3 + a2)  * e2.y;
            const float na4 = (a4 + a3)               * eb;
            a0 = na0; a1 = na1; a2 = na2; a3 = na3; a4 = na4;
        };
        auto fwd_chunk = [&](const float2 (&e2)[DPCH], const float (&eb)[DPCH], int j0) {
#pragma unroll
            for (int j = 0; j < DPCH; j++) {
                if (j >= j0) {
                    fwd_step(e2[j], eb[j]);
                    if ((j & 3) == 3) renorm();
                }
            }
        };

        waitflag(0);
        load_f(0, e2A, ebA);
        waitflag(1);
        load_f(1, e2B, ebB);

        a0 = (lane == 0) ? ebA[0]   : 0.f;
        a1 = (lane == 0) ? e2A[0].x : 0.f;
        a2 = 0.f; a3 = 0.f; a4 = 0.f;
        E  = (lane == 0) ? 0 : ESENT;
        fwd_chunk(e2A, ebA, 1);

        for (int k = 1; k < NIT; k++) {
            if (k & 1) {
                if (k + 1 < NIT) { waitflag(k + 1); load_f(k + 1, e2A, ebA); }
                fwd_chunk(e2B, ebB, 0);
            } else {
                if (k + 1 < NIT) { waitflag(k + 1); load_f(k + 1, e2B, ebB); }
                fwd_chunk(e2A, ebA, 0);
            }
        }
    } else {
        // ---------------- BACKWARD WARP ----------------
        auto waitb = [&](int k) {
            const int hi = (tl - 1 - DPCH * k) >> 3;
            const int lo = (tl - DPCH - DPCH * k) >> 3;
            waitflag(hi);
            if (lo != hi) waitflag(lo);
        };
        auto load_b = [&](int k, float2 (&e2)[DPCH], float (&eb)[DPCH]) {
#pragma unroll
            for (int j = 0; j < DPCH; j++) {
                const float* r = ebase + (size_t)(tl - 1 - (k * DPCH + j)) * ROWE;
                e2[j] = __ldg((const float2*)r + lane);
                eb[j] = __ldg(r + CTC_L);
            }
        };
        auto bwd_step = [&](const float2 e2, const float eb) {
            const float p1  = e2.x * a1;
            const float p3  = e2.y * a3;
            const float pb0 = eb * a0;
            const float pb2 = eb * a2;
            const float pb4 = eb * a4;          // lane31: state 128
            const float z = fmaf(sk1, p1, pb0); // export to lane l-1
            float zin = __shfl_down_sync(0xffffffffu, z, 1);
            int   Ep  = __shfl_down_sync(0xffffffffu, E, 1);
            zin = (lane == 31) ? pb4 : zin;     // s=127 -> s=128 (own)
            Ep  = (lane == 31) ? E   : Ep;
            const int   En = max(E, Ep);
            const float f1 = __int_as_float(max(127 + (E  - En), 0) << 23);
            const float f2 = __int_as_float(max(127 + (Ep - En), 0) << 23);
            const float nb0 = (pb0 + p1)              * f1;
            const float nb1 = fmaf(sk3, p3, p1 + pb2) * f1;
            const float nb2 = (pb2 + p3)              * f1;
            const float nb3 = fmaf(zin, f2, p3 * f1);
            const float nb4 = pb4 * f1;
            a0 = nb0; a1 = nb1; a2 = nb2; a3 = nb3; a4 = nb4;
            E = En;
        };
        auto bwd_chunk = [&](const float2 (&e2)[DPCH], const float (&eb)[DPCH]) {
#pragma unroll
            for (int j = 0; j < DPCH; j++) {
                bwd_step(e2[j], eb[j]);
                if ((j & 3) == 3) renorm();
            }
        };

        // beta init at t = tl-1: indicator of final states
        const int se = 2 * ll, sm = se - 1;
        const int s0i = 4 * lane;
        a0 = (s0i == se || s0i == sm) ? 1.f : 0.f;
        a1 = (s0i + 1 == se || s0i + 1 == sm) ? 1.f : 0.f;
        a2 = (s0i + 2 == se || s0i + 2 == sm) ? 1.f : 0.f;
        a3 = (s0i + 3 == se || s0i + 3 == sm) ? 1.f : 0.f;
        a4 = (lane == 31 && se == 128) ? 1.f : 0.f;
        E = (a0 + a1 + a2 + a3 + a4 > 0.f) ? 0 : ESENT;

        waitb(0);
        load_b(0, e2A, ebA);
        waitb(1);
        load_b(1, e2B, ebB);
        bwd_chunk(e2A, ebA);
        for (int k = 1; k < NIT; k++) {
            if (k & 1) {
                if (k + 1 < NIT) { waitb(k + 1); load_b(k + 1, e2A, ebA); }
                bwd_chunk(e2B, ebB);
            } else {
                if (k + 1 < NIT) { waitb(k + 1); load_b(k + 1, e2B, ebB); }
                bwd_chunk(e2A, ebA);
            }
        }
    }

    // -------- rendezvous + combine --------
    sv[w][0][lane] = a0; sv[w][1][lane] = a1; sv[w][2][lane] = a2;
    sv[w][3][lane] = a3; sv[w][4][lane] = a4; sEx[w][lane] = E;
    barsync(2, 64);

    if (w == 0) {
        const float b0 = sv[1][0][lane], b1 = sv[1][1][lane],
                    b2 = sv[1][2][lane], b3 = sv[1][3][lane],
                    b4 = sv[1][4][lane];
        const int EB = sEx[1][lane];
        float dot = a0 * b0 + a1 * b1 + a2 * b2 + a3 * b3;
        if (lane == 31) dot += a4 * b4;
        float l2d = (dot > 0.f) ? (__log2f(dot) + (float)(E + EB)) : -1e30f;
        const float m = warpmaxf(l2d);
        const float ssum = warpsum(exp2f(l2d - m));

        unsigned done = 0;
        if (lane == 0) {
            g_nll[b] = -LN2 * (m + __log2f(ssum));
            __threadfence();
            done = (atomicAdd(&g_count, 1u) == CTC_B - 1) ? 1u : 0u;
        }
        done = __shfl_sync(0xffffffffu, done, 0);
        if (done) {
            // last DP block: reset flags for next graph replay
            int4 z = make_int4(0, 0, 0, 0);
            int4* f4 = (int4*)g_flag;
#pragma unroll 4
            for (int i = lane; i < (CTC_B * NCHNK) / 4; i += 32) f4[i] = z;
            // deterministic fixed-tree mean
            float s = 0.f;
#pragma unroll
            for (int i = 0; i < CTC_B / 32; i++)
                s += __ldcg(&g_nll[i * 32 + lane]);
            s = warpsum(s);
            if (lane == 0) {
                out[0] = s * (1.0f / CTC_B);
                __threadfence();
                g_count = 0;             // reset for next graph replay
            }
        }
    }
}

extern "C" void kernel_launch(void* const* d_in, const int* in_sizes, int n_in,
                              void* d_out, int out_size)
{
    const float* logits       = (const float*)d_in[0];
    const int*   labels       = (const int*)d_in[1];
    const int*   label_length = (const int*)d_in[2];
    const int*   logit_length = (const int*)d_in[3];

    const int grid = CTC_B + (CTC_B * CTC_T) / DPCH;   // 256 DP + 8192 emit
    ctc_fused_kernel<<<grid, 256>>>(logits, labels, label_length, logit_length,
                                    (float*)d_out);
    (void)in_sizes; (void)n_in; (void)out_size;
}

// round 16
// speedup vs baseline: 1.7427x; 1.7427x over previous
#include <cuda_runtime.h>

// Problem constants
#define CTC_B 256
#define CTC_T 256
#define CTC_C 512
#define CTC_L 64
#define ROWE  66            // g_emit floats per row: 64 label probs + blank + pad
#define LOG2E 1.4426950408889634f
#define LN2   0.6931471805599453f
#define DPCH  8             // DP prefetch chunk (rows) = 2 windows
#define ESENT (-(1 << 28))  // exponent sentinel for massless lanes

__device__ float g_emit[(size_t)CTC_B * CTC_T * ROWE];   // softmax PROBS (~17 MB)
__device__ float g_nll[CTC_B];
__device__ unsigned int g_count = 0;

__device__ __forceinline__ float warpsum(float v) {
#pragma unroll
    for (int o = 16; o; o >>= 1) v += __shfl_xor_sync(0xffffffffu, v, o);
    return v;
}
__device__ __forceinline__ float warpmaxf(float v) {
#pragma unroll
    for (int o = 16; o; o >>= 1) v = fmaxf(v, __shfl_xor_sync(0xffffffffu, v, o));
    return v;
}

// Kernel 1 (validated R8-R14): per (b,t) row softmax over C=512, write 65
// needed probabilities (64 label slots + blank). One warp per row.
__global__ void __launch_bounds__(256) lse_emit_kernel(
    const float* __restrict__ logits, const int* __restrict__ labels)
{
    __shared__ float srow[8][CTC_C];
    __shared__ int   slab[CTC_L];
    const int w    = threadIdx.x >> 5;
    const int lane = threadIdx.x & 31;
    const int row_id = blockIdx.x * 8 + w;          // = b*T + t
    const int b = blockIdx.x >> 5;                  // 32 blocks per batch

    if (threadIdx.x < CTC_L) slab[threadIdx.x] = labels[b * CTC_L + threadIdx.x];

    const float4* row4 = (const float4*)(logits + (size_t)row_id * CTC_C);
    float4 v[4];
#pragma unroll
    for (int k = 0; k < 4; k++) v[k] = row4[k * 32 + lane];

    float s = 0.f;
#pragma unroll
    for (int k = 0; k < 4; k++) {
        const float e0 = exp2f(v[k].x * LOG2E);
        const float e1 = exp2f(v[k].y * LOG2E);
        const float e2 = exp2f(v[k].z * LOG2E);
        const float e3 = exp2f(v[k].w * LOG2E);
        const int i4 = (k * 32 + lane) * 4;
        srow[w][i4 + 0] = e0; srow[w][i4 + 1] = e1;
        srow[w][i4 + 2] = e2; srow[w][i4 + 3] = e3;
        s += e0 + e1 + e2 + e3;
    }
    s = warpsum(s);
    const float rcp = __frcp_rn(s);
    __syncthreads();

    float* eout = g_emit + (size_t)row_id * ROWE;
    eout[lane]      = srow[w][slab[lane]]      * rcp;
    eout[32 + lane] = srow[w][slab[32 + lane]] * rcp;
    if (lane == 0)
        eout[CTC_L] = srow[w][CTC_C - 1] * rcp;      // blank = last class
}

// Kernel 2: bidirectional CTC DP with WINDOWED exponent exchange: E is
// exchanged once per 4-step window (it only changes at renorm), so each
// step needs a single mantissa shuffle + one constant-factor multiply.
// fp32 probability domain, per-lane exponents (R9-R13 validated machinery).
// One block (2 warps) per batch: warp 0 fwd over [0,tm), warp 1 bwd over
// [tl-1, tm]. p = sum_s alpha(s)*beta(s) at t = tm-1.
__global__ void __launch_bounds__(64) ctc_dp_kernel(
    const int* __restrict__ labels,
    const int* __restrict__ label_length,
    const int* __restrict__ logit_length,
    float* __restrict__ out)
{
    __shared__ int   slab[CTC_L];
    __shared__ float sv[2][5][32];
    __shared__ int   sEx[2][32];

    const int b    = blockIdx.x;
    const int tid  = threadIdx.x;
    const int w    = tid >> 5;       // 0 = forward, 1 = backward
    const int lane = tid & 31;

    slab[tid] = labels[b * CTC_L + tid];    // 64 threads = 64 labels
    __syncthreads();

    const int tl = logit_length[b];         // == 256 here
    const int ll = label_length[b];
    const int tm = tl >> 1;
    const int NIT = tm / DPCH;              // 16 chunks per direction

    const float sk1 = ((4 * lane + 1) >= 3 && slab[2 * lane] != slab[2 * lane - 1]) ? 1.f : 0.f;
    const float sk3 = (slab[2 * lane + 1] != slab[2 * lane]) ? 1.f : 0.f;

    const float* ebase = g_emit + (size_t)b * CTC_T * ROWE;

    float2 e2A[DPCH], e2B[DPCH];
    float  ebA[DPCH], ebB[DPCH];

    float a0, a1, a2, a3, a4;
    int E;

    // branchless per-lane renorm (m==0 -> ex=-127, sentinel drifts lower)
    auto renorm = [&]() {
        const float m = fmaxf(fmaxf(fmaxf(a0, a1), fmaxf(a2, a3)), a4);
        const int ex = (__float_as_int(m) >> 23) - 127;
        const float r = __int_as_float((127 - ex) << 23);
        a0 *= r; a1 *= r; a2 *= r; a3 *= r; a4 *= r;
        E += ex;
    };

    if (w == 0) {
        // ================= FORWARD WARP =================
        auto load_f = [&](int k, float2 (&e2)[DPCH], float (&eb)[DPCH]) {
#pragma unroll
            for (int j = 0; j < DPCH; j++) {
                const float* r = ebase + (size_t)(k * DPCH + j) * ROWE;
                e2[j] = __ldg((const float2*)r + lane);
                eb[j] = __ldg(r + CTC_L);
            }
        };
        // classic single step with full E exchange (chunk-0 prologue only)
        auto fwd_single = [&](const float2 e2, const float eb) {
            float am1 = __shfl_up_sync(0xffffffffu, a3, 1);
            int   Ep  = __shfl_up_sync(0xffffffffu, E,  1);
            am1 = (lane == 0) ? 0.f : am1;
            Ep  = (lane == 0) ? E   : Ep;
            const int   En = max(E, Ep);
            const float f1 = __int_as_float(max(127 + (E  - En), 0) << 23);
            const float f2 = __int_as_float(max(127 + (Ep - En), 0) << 23);
            am1 *= f2;
            a0 *= f1; a1 *= f1; a2 *= f1; a3 *= f1; a4 *= f1;
            E = En;
            const float na0 = (a0 + am1)              * eb;
            const float na1 = fmaf(sk1, am1, a1 + a0) * e2.x;
            const float na2 = (a2 + a1)               * eb;
            const float na3 = fmaf(sk3, a1, a3 + a2)  * e2.y;
            const float na4 = (a4 + a3)               * eb;
            a0 = na0; a1 = na1; a2 = na2; a3 = na3; a4 = na4;
        };
        // 4-step window: one E exchange, constant f2, renorm at end
        auto fwd_win4 = [&](const float2 (&e2)[DPCH], const float (&eb)[DPCH],
                            const int o) {
            int Ep = __shfl_up_sync(0xffffffffu, E, 1);
            Ep = (lane == 0) ? E : Ep;
            const int En = max(E, Ep);
            int Enp = __shfl_up_sync(0xffffffffu, En, 1);
            Enp = (lane == 0) ? En : Enp;
            const float f1 = __int_as_float(max(127 + (E - En), 0) << 23);
            const float f2 = __int_as_float(
                min(max(127 + (Enp - En), 0), 254) << 23);
            a0 *= f1; a1 *= f1; a2 *= f1; a3 *= f1; a4 *= f1;
            E = En;
#pragma unroll
            for (int j = 0; j < 4; j++) {
                float am1 = __shfl_up_sync(0xffffffffu, a3, 1);
                am1 = (lane == 0) ? 0.f : am1;
                am1 *= f2;
                const float na0 = (a0 + am1)              * eb[o + j];
                const float na1 = fmaf(sk1, am1, a1 + a0) * e2[o + j].x;
                const float na2 = (a2 + a1)               * eb[o + j];
                const float na3 = fmaf(sk3, a1, a3 + a2)  * e2[o + j].y;
                const float na4 = (a4 + a3)               * eb[o + j];
                a0 = na0; a1 = na1; a2 = na2; a3 = na3; a4 = na4;
            }
            renorm();
        };

        load_f(0, e2A, ebA);
        load_f(1, e2B, ebB);

        // chunk 0: init (t=0), singles t=1..3, renorm, window t=4..7
        a0 = (lane == 0) ? ebA[0]   : 0.f;
        a1 = (lane == 0) ? e2A[0].x : 0.f;
        a2 = 0.f; a3 = 0.f; a4 = 0.f;
        E  = (lane == 0) ? 0 : ESENT;
        fwd_single(e2A[1], ebA[1]);
        fwd_single(e2A[2], ebA[2]);
        fwd_single(e2A[3], ebA[3]);
        renorm();
        fwd_win4(e2A, ebA, 4);

        for (int k = 1; k < NIT; k++) {
            if (k & 1) {
                if (k + 1 < NIT) load_f(k + 1, e2A, ebA);
                fwd_win4(e2B, ebB, 0);
                fwd_win4(e2B, ebB, 4);
            } else {
                if (k + 1 < NIT) load_f(k + 1, e2B, ebB);
                fwd_win4(e2A, ebA, 0);
                fwd_win4(e2A, ebA, 4);
            }
        }
    } else {
        // ================= BACKWARD WARP =================
        auto load_b = [&](int k, float2 (&e2)[DPCH], float (&eb)[DPCH]) {
#pragma unroll
            for (int j = 0; j < DPCH; j++) {
                const float* r = ebase + (size_t)(tl - 1 - (k * DPCH + j)) * ROWE;
                e2[j] = __ldg((const float2*)r + lane);
                eb[j] = __ldg(r + CTC_L);
            }
        };
        // 4-step window, one E exchange (shfl_down direction)
        auto bwd_win4 = [&](const float2 (&e2)[DPCH], const float (&eb)[DPCH],
                            const int o) {
            int Ep = __shfl_down_sync(0xffffffffu, E, 1);
            Ep = (lane == 31) ? E : Ep;
            const int En = max(E, Ep);
            int Enp = __shfl_down_sync(0xffffffffu, En, 1);
            Enp = (lane == 31) ? En : Enp;
            const float f1 = __int_as_float(max(127 + (E - En), 0) << 23);
            const float f2 = __int_as_float(
                min(max(127 + (Enp - En), 0), 254) << 23);
            a0 *= f1; a1 *= f1; a2 *= f1; a3 *= f1; a4 *= f1;
            E = En;
#pragma unroll
            for (int j = 0; j < 4; j++) {
                const float p1  = e2[o + j].x * a1;
                const float p3  = e2[o + j].y * a3;
                const float pb0 = eb[o + j] * a0;
                const float pb2 = eb[o + j] * a2;
                const float pb4 = eb[o + j] * a4;       // lane31: state 128
                const float z = fmaf(sk1, p1, pb0);     // export to lane l-1
                float zin = __shfl_down_sync(0xffffffffu, z, 1);
                zin *= f2;
                zin = (lane == 31) ? pb4 : zin;         // s=127 -> s=128 (own)
                a0 = pb0 + p1;
                a1 = fmaf(sk3, p3, p1 + pb2);
                a2 = pb2 + p3;
                a3 = p3 + zin;
                a4 = pb4;
            }
            renorm();
        };

        // beta init at t = tl-1: indicator of final states
        const int se = 2 * ll, sm = se - 1;
        const int s0i = 4 * lane;
        a0 = (s0i == se || s0i == sm) ? 1.f : 0.f;
        a1 = (s0i + 1 == se || s0i + 1 == sm) ? 1.f : 0.f;
        a2 = (s0i + 2 == se || s0i + 2 == sm) ? 1.f : 0.f;
        a3 = (s0i + 3 == se || s0i + 3 == sm) ? 1.f : 0.f;
        a4 = (lane == 31 && se == 128) ? 1.f : 0.f;
        E = (a0 + a1 + a2 + a3 + a4 > 0.f) ? 0 : ESENT;

        load_b(0, e2A, ebA);
        load_b(1, e2B, ebB);
        bwd_win4(e2A, ebA, 0);
        bwd_win4(e2A, ebA, 4);
        for (int k = 1; k < NIT; k++) {
            if (k & 1) {
                if (k + 1 < NIT) load_b(k + 1, e2A, ebA);
                bwd_win4(e2B, ebB, 0);
                bwd_win4(e2B, ebB, 4);
            } else {
                if (k + 1 < NIT) load_b(k + 1, e2B, ebB);
                bwd_win4(e2A, ebA, 0);
                bwd_win4(e2A, ebA, 4);
            }
        }
    }

    // -------- rendezvous + combine --------
    sv[w][0][lane] = a0; sv[w][1][lane] = a1; sv[w][2][lane] = a2;
    sv[w][3][lane] = a3; sv[w][4][lane] = a4; sEx[w][lane] = E;
    __syncthreads();

    if (w == 0) {
        const float b0 = sv[1][0][lane], b1 = sv[1][1][lane],
                    b2 = sv[1][2][lane], b3 = sv[1][3][lane],
                    b4 = sv[1][4][lane];
        const int EB = sEx[1][lane];
        float dot = a0 * b0 + a1 * b1 + a2 * b2 + a3 * b3;
        if (lane == 31) dot += a4 * b4;
        float l2d = (dot > 0.f) ? (__log2f(dot) + (float)(E + EB)) : -1e30f;
        const float m = warpmaxf(l2d);
        const float ssum = warpsum(exp2f(l2d - m));

        unsigned done = 0;
        if (lane == 0) {
            g_nll[b] = -LN2 * (m + __log2f(ssum));
            __threadfence();
            done = (atomicAdd(&g_count, 1u) == CTC_B - 1) ? 1u : 0u;
        }
        done = __shfl_sync(0xffffffffu, done, 0);
        if (done) {
            float s = 0.f;
#pragma unroll
            for (int i = 0; i < CTC_B / 32; i++)
                s += __ldcg(&g_nll[i * 32 + lane]);
            s = warpsum(s);
            if (lane == 0) {
                out[0] = s * (1.0f / CTC_B);
                g_count = 0;             // reset for next graph replay
            }
        }
    }
}

extern "C" void kernel_launch(void* const* d_in, const int* in_sizes, int n_in,
                              void* d_out, int out_size)
{
    const float* logits       = (const float*)d_in[0];
    const int*   labels       = (const int*)d_in[1];
    const int*   label_length = (const int*)d_in[2];
    const int*   logit_length = (const int*)d_in[3];

    lse_emit_kernel<<<(CTC_B * CTC_T) / 8, 256>>>(logits, labels);
    ctc_dp_kernel<<<CTC_B, 64>>>(labels, label_length, logit_length, (float*)d_out);
    (void)in_sizes; (void)n_in; (void)out_size;
}